// round 3
// baseline (speedup 1.0000x reference)
#include <cuda_runtime.h>

typedef unsigned long long ull;

#define BB 256
#define TT 2048
#define TB (TT * BB)

// layer-0 output scratch: h1[t][b][64]  (fwd -> [0:32), bwd -> [32:64))
__device__ float g_h1[(size_t)TT * BB * 64];
// precomputed gate bases: xg[dir][t][b][128], interleaved as lane*4+gate (i,f,g,o)
__device__ float g_xg[(size_t)2 * TT * BB * 128];

__device__ __forceinline__ float sigf(float x) {
    return __fdividef(1.0f, 1.0f + __expf(-x));
}
__device__ __forceinline__ float tanh_fast(float x) {
    return 1.0f - __fdividef(2.0f, __expf(2.0f * x) + 1.0f);
}
__device__ __forceinline__ ull pack2(float lo, float hi) {
    ull r;
    asm("mov.b64 %0, {%1, %2};" : "=l"(r) : "f"(lo), "f"(hi));
    return r;
}
__device__ __forceinline__ void unpack2(ull v, float& lo, float& hi) {
    asm("mov.b64 {%0, %1}, %2;" : "=f"(lo), "=f"(hi) : "l"(v));
}
__device__ __forceinline__ ull ffma2(ull a, ull b, ull c) {
    ull d;
    asm("fma.rn.f32x2 %0, %1, %2, %3;" : "=l"(d) : "l"(a), "l"(b), "l"(c));
    return d;
}

// ---------------------------------------------------------------------------
// Precompute: xg[dir][m][128] = W_ih[dir] @ x[m] + b_ih + b_hh   (m = t*BB+b)
// 256 threads: gate row = tid&127, grp = tid>>7 handles 4 of 8 rows per tile.
// ---------------------------------------------------------------------------
template<int F, bool L0>
__global__ __launch_bounds__(256, 1)
void precompute(const float* __restrict__ oseq,  // [B,T,16] (L0 only)
                const float* __restrict__ iseq,  // [B,T,16] (L0 only)
                const float* __restrict__ Wih,   // [2,128,F]
                const float* __restrict__ bih,
                const float* __restrict__ bhh)
{
    const int dir = blockIdx.y;
    const int tid = threadIdx.x;
    const int r   = tid & 127;   // gate row (PyTorch: i,f,g,o x 32)
    const int grp = tid >> 7;

    ull w[F / 2];
    {
        const float* p = Wih + (size_t)(dir * 128 + r) * F;
        #pragma unroll
        for (int k = 0; k < F / 2; k++) w[k] = pack2(p[2 * k], p[2 * k + 1]);
    }
    const float bias = bih[dir * 128 + r] + bhh[dir * 128 + r];

    __shared__ __align__(16) float x_sh[8][F];
    __shared__ __align__(16) float o_sh[8][128];

    const int ocol = ((r & 31) << 2) | (r >> 5);   // interleaved column

    for (int m0 = blockIdx.x * 8; m0 < TB; m0 += gridDim.x * 8) {
        // stage x for 8 rows
        if (L0) {
            if (tid < 64) {
                const int row = tid >> 3, seg = tid & 7;
                const int m = m0 + row, t = m >> 8, b = m & 255;
                float4 v;
                if (seg < 4) v = *(const float4*)&oseq[((size_t)b * TT + t) * 16 + seg * 4];
                else         v = *(const float4*)&iseq[((size_t)b * TT + (TT - 1 - t)) * 16 + (seg - 4) * 4];
                *(float4*)&x_sh[row][seg * 4] = v;
            }
        } else {
            if (tid < 128) {
                const int row = tid >> 4, seg = tid & 15;
                *(float4*)&x_sh[row][seg * 4] =
                    *(const float4*)&g_h1[(size_t)(m0 + row) * 64 + seg * 4];
            }
        }
        __syncthreads();

        // compute 4 rows per thread
        ull acc[4];
        #pragma unroll
        for (int rr = 0; rr < 4; rr++) acc[rr] = 0ull;
        #pragma unroll
        for (int k2 = 0; k2 < F / 4; k2++) {
            #pragma unroll
            for (int rr = 0; rr < 4; rr++) {
                const float4 v = *(const float4*)&x_sh[grp * 4 + rr][k2 * 4];
                acc[rr] = ffma2(w[2 * k2],     pack2(v.x, v.y), acc[rr]);
                acc[rr] = ffma2(w[2 * k2 + 1], pack2(v.z, v.w), acc[rr]);
            }
        }
        #pragma unroll
        for (int rr = 0; rr < 4; rr++) {
            float lo, hi;
            unpack2(acc[rr], lo, hi);
            o_sh[grp * 4 + rr][ocol] = lo + hi + bias;
        }
        __syncthreads();

        // coalesced store: 8 rows x 128 floats = 256 threads x float4
        {
            const int row = tid >> 5, col = (tid * 4) & 127;
            *(float4*)&g_xg[((size_t)dir * TB + m0 + row) * 128 + col] =
                *(const float4*)&o_sh[row][col];
        }
        // next tile's x_sh write is ordered by the first __syncthreads
    }
}

// ---------------------------------------------------------------------------
// Recurrent: warp-per-batch, barrier-free. Lane l owns cell l (gate rows
// l, 32+l, 64+l, 96+l). xg prefetched 4 steps ahead (LDG.128, coalesced).
// ---------------------------------------------------------------------------
template<bool L0K>
__global__ __launch_bounds__(128)
void recurrent(const float* __restrict__ Whh,   // [2,128,32]
               float* __restrict__ outp)        // L1: d_out [B,T,64]
{
    const int dir  = blockIdx.y;
    const int warp = threadIdx.x >> 5;
    const int lane = threadIdx.x & 31;
    const int b    = blockIdx.x * 4 + warp;

    ull w[4][16];
    #pragma unroll
    for (int g = 0; g < 4; g++) {
        const float* p = Whh + (size_t)(dir * 128 + g * 32 + lane) * 32;
        #pragma unroll
        for (int k = 0; k < 16; k++) w[g][k] = pack2(p[2 * k], p[2 * k + 1]);
    }

    __shared__ __align__(16) float h_sh[4][2][32];
    h_sh[warp][0][lane] = 0.0f;
    float c = 0.0f;
    __syncwarp();

    const float* xgp = g_xg + ((size_t)dir * TB + (size_t)(dir ? (TT - 1) * BB : 0) + b) * 128
                     + lane * 4;
    const long long stp = (dir ? -(long long)BB : (long long)BB) * 128;

    float4 b0 = *(const float4*)(xgp + 0 * stp);
    float4 b1 = *(const float4*)(xgp + 1 * stp);
    float4 b2 = *(const float4*)(xgp + 2 * stp);
    float4 b3 = *(const float4*)(xgp + 3 * stp);

    auto step = [&](int s, float4& bf, int cb) {
        const float4 xg4 = bf;
        if (s + 4 < TT) bf = *(const float4*)(xgp + (long long)(s + 4) * stp);

        ull aA[4], aB[4];
        #pragma unroll
        for (int g = 0; g < 4; g++) { aA[g] = 0ull; aB[g] = 0ull; }

        const float4* hp = (const float4*)h_sh[warp][cb];
        #pragma unroll
        for (int k4 = 0; k4 < 4; k4++) {
            const float4 hv = hp[k4];
            const ull lo = pack2(hv.x, hv.y), hi = pack2(hv.z, hv.w);
            #pragma unroll
            for (int g = 0; g < 4; g++) {
                aA[g] = ffma2(w[g][2 * k4],     lo, aA[g]);
                aB[g] = ffma2(w[g][2 * k4 + 1], hi, aB[g]);
            }
        }
        #pragma unroll
        for (int k4 = 4; k4 < 8; k4++) {
            const float4 hv = hp[k4];
            const ull lo = pack2(hv.x, hv.y), hi = pack2(hv.z, hv.w);
            #pragma unroll
            for (int g = 0; g < 4; g++) {
                aA[g] = ffma2(w[g][2 * k4],     lo, aA[g]);
                aB[g] = ffma2(w[g][2 * k4 + 1], hi, aB[g]);
            }
        }

        float gv[4];
        const float xgc[4] = {xg4.x, xg4.y, xg4.z, xg4.w};
        #pragma unroll
        for (int g = 0; g < 4; g++) {
            float l0, h0, l1, h1;
            unpack2(aA[g], l0, h0);
            unpack2(aB[g], l1, h1);
            gv[g] = xgc[g] + ((l0 + h0) + (l1 + h1));
        }

        const float fo = sigf(gv[3]);
        const float fg = tanh_fast(gv[2]);
        const float fi = sigf(gv[0]);
        const float ff = sigf(gv[1]);
        c = ff * c + fi * fg;
        const float h = fo * tanh_fast(c);
        h_sh[warp][cb ^ 1][lane] = h;

        const int t = dir ? (TT - 1 - s) : s;
        if (L0K) g_h1[((size_t)t * BB + b) * 64 + dir * 32 + lane] = h;
        else     outp[((size_t)b * TT + t) * 64 + dir * 32 + lane] = h;
        __syncwarp();
    };

    for (int s = 0; s < TT; s += 4) {
        step(s + 0, b0, 0);
        step(s + 1, b1, 1);
        step(s + 2, b2, 0);
        step(s + 3, b3, 1);
    }
}

extern "C" void kernel_launch(void* const* d_in, const int* in_sizes, int n_in,
                              void* d_out, int out_size) {
    (void)in_sizes; (void)n_in; (void)out_size;
    const float* oseq = (const float*)d_in[0];
    const float* iseq = (const float*)d_in[1];
    const float* Wih0 = (const float*)d_in[2];
    const float* Whh0 = (const float*)d_in[3];
    const float* bih0 = (const float*)d_in[4];
    const float* bhh0 = (const float*)d_in[5];
    const float* Wih1 = (const float*)d_in[6];
    const float* Whh1 = (const float*)d_in[7];
    const float* bih1 = (const float*)d_in[8];
    const float* bhh1 = (const float*)d_in[9];
    float* out = (float*)d_out;

    dim3 pgrid(148, 2);
    dim3 rgrid(BB / 4, 2);

    precompute<32, true ><<<pgrid, 256>>>(oseq, iseq, Wih0, bih0, bhh0);
    recurrent<true ><<<rgrid, 128>>>(Whh0, nullptr);
    precompute<64, false><<<pgrid, 256>>>(nullptr, nullptr, Wih1, bih1, bhh1);
    recurrent<false><<<rgrid, 128>>>(Whh1, out);
}

// round 4
// speedup vs baseline: 1.3487x; 1.3487x over previous
#include <cuda_runtime.h>

typedef unsigned long long ull;

#define BB 256
#define TT 2048
#define TB (TT * BB)

// layer-0 output: h1[t][b][64]  (fwd -> [0:32), bwd -> [32:64))
__device__ float g_h1[(size_t)TT * BB * 64];
// precomputed gate bases, plain PyTorch gate order: xg[dir][m][128], m = t*BB+b
__device__ float g_xg[(size_t)2 * TT * BB * 128];

__device__ __forceinline__ float sigf(float x) {
    return __fdividef(1.0f, 1.0f + __expf(-x));
}
__device__ __forceinline__ float tanh_fast(float x) {
    return 1.0f - __fdividef(2.0f, __expf(2.0f * x) + 1.0f);
}
__device__ __forceinline__ void unpack2(ull v, float& lo, float& hi) {
    asm("mov.b64 {%0, %1}, %2;" : "=f"(lo), "=f"(hi) : "l"(v));
}
__device__ __forceinline__ ull ffma2(ull a, ull b, ull c) {
    ull d;
    asm("fma.rn.f32x2 %0, %1, %2, %3;" : "=l"(d) : "l"(a), "l"(b), "l"(c));
    return d;
}
__device__ __forceinline__ ull fadd2(ull a, ull b) {
    ull d;
    asm("add.rn.f32x2 %0, %1, %2;" : "=l"(d) : "l"(a), "l"(b));
    return d;
}

// ---------------------------------------------------------------------------
// Precompute: xg[dir][m][r] = W_ih[dir][r] . x[m] + b_ih[r] + b_hh[r]
// 256 threads = 2 groups x 128 gate rows. Tile = 1024/F tokens, double-buffered
// x in smem, weight rows stationary in registers (as ull pairs, no MOV packs).
// Output stores are coalesced STG.32 (lanes = consecutive gate rows).
// ---------------------------------------------------------------------------
template<int F, bool L0>
__global__ __launch_bounds__(256)
void precompute(const float* __restrict__ oseq,  // [B,T,16] (L0 only)
                const float* __restrict__ iseq,  // [B,T,16] (L0 only)
                const float* __restrict__ Wih,   // [2,128,F]
                const float* __restrict__ bih,
                const float* __restrict__ bhh)
{
    constexpr int TM = 1024 / F;   // tokens per tile (32 for F=32, 16 for F=64)
    constexpr int TG = TM / 2;     // tokens per group
    const int dir = blockIdx.y;
    const int tid = threadIdx.x;
    const int r   = tid & 127;     // gate row (PyTorch order)
    const int grp = tid >> 7;

    ull w[F / 2];
    {
        const ull* wp = (const ull*)(Wih + (size_t)(dir * 128 + r) * F);
        #pragma unroll
        for (int k = 0; k < F / 2; k++) w[k] = wp[k];
    }
    const float bias = bih[dir * 128 + r] + bhh[dir * 128 + r];

    __shared__ __align__(16) float x_sh[2][TM][F];

    const int stride = 148 * TM;
    const int srow = tid / (F / 4);
    const int sseg = tid % (F / 4);

    auto stage = [&](int m0, int buf) {
        const int m = m0 + srow;
        float4 v;
        if (L0) {
            const int t = m >> 8, bb = m & 255;
            if (sseg < 4) v = *(const float4*)&oseq[((size_t)bb * TT + t) * 16 + sseg * 4];
            else          v = *(const float4*)&iseq[((size_t)bb * TT + (TT - 1 - t)) * 16 + (sseg - 4) * 4];
        } else {
            v = *(const float4*)&g_h1[(size_t)m * 64 + sseg * 4];
        }
        *(float4*)&x_sh[buf][srow][sseg * 4] = v;
    };

    int buf = 0;
    int m0 = blockIdx.x * TM;
    if (m0 < TB) stage(m0, 0);

    float* const xg = g_xg + (size_t)dir * TB * 128;

    for (; m0 < TB; m0 += stride) {
        __syncthreads();
        const int mn = m0 + stride;
        if (mn < TB) stage(mn, buf ^ 1);

        ull acc[TG];
        #pragma unroll
        for (int i = 0; i < TG; i++) acc[i] = 0ull;

        const ulonglong2* xp = (const ulonglong2*)&x_sh[buf][grp * TG][0];
        #pragma unroll
        for (int j = 0; j < F / 4; j++) {        // one ulonglong2 = 2 float pairs
            #pragma unroll
            for (int i = 0; i < TG; i++) {
                const ulonglong2 v = xp[i * (F / 4) + j];
                acc[i] = ffma2(w[2 * j],     v.x, acc[i]);
                acc[i] = ffma2(w[2 * j + 1], v.y, acc[i]);
            }
        }

        #pragma unroll
        for (int i = 0; i < TG; i++) {
            float lo, hi;
            unpack2(acc[i], lo, hi);
            xg[(size_t)(m0 + grp * TG + i) * 128 + r] = (lo + hi) + bias;
        }
        buf ^= 1;
    }
}

// ---------------------------------------------------------------------------
// Recurrent: warp-per-(batch,dir), 4 warps/block, 128 blocks. Lane l owns cell
// l (gate rows l, 32+l, 64+l, 96+l). h exchange via double-buffered smem
// (LDS.128 pair loads, no packs). xg prefetched 4 steps (4 coalesced LDG.32).
// ---------------------------------------------------------------------------
template<bool L0K>
__global__ __launch_bounds__(128)
void recurrent(const float* __restrict__ Whh,   // [2,128,32]
               float* __restrict__ outp)        // L1: d_out [B,T,64]
{
    const int dir  = blockIdx.y;
    const int warp = threadIdx.x >> 5;
    const int lane = threadIdx.x & 31;
    const int b    = blockIdx.x * 4 + warp;

    ull w[4][16];
    #pragma unroll
    for (int g = 0; g < 4; g++) {
        const ull* p = (const ull*)(Whh + (size_t)(dir * 128 + g * 32 + lane) * 32);
        #pragma unroll
        for (int k = 0; k < 16; k++) w[g][k] = p[k];
    }

    __shared__ __align__(16) float h_sh[4][2][32];
    h_sh[warp][0][lane] = 0.0f;
    float c = 0.0f;
    __syncwarp();

    const float* xbase = g_xg + ((size_t)dir * TB + (size_t)(dir ? (TT - 1) * BB : 0) + b) * 128
                       + lane;
    const long long stp = (dir ? -(long long)BB : (long long)BB) * 128;

    float xf[4][4];
    #pragma unroll
    for (int d = 0; d < 4; d++) {
        const float* p = xbase + (long long)d * stp;
        xf[d][0] = p[0]; xf[d][1] = p[32]; xf[d][2] = p[64]; xf[d][3] = p[96];
    }

    auto step = [&](int s, int d, int cb) {
        float gi = xf[d][0], gf = xf[d][1], gg = xf[d][2], go = xf[d][3];
        if (s + 4 < TT) {
            const float* p = xbase + (long long)(s + 4) * stp;
            xf[d][0] = p[0]; xf[d][1] = p[32]; xf[d][2] = p[64]; xf[d][3] = p[96];
        }

        const ulonglong2* hp = (const ulonglong2*)h_sh[warp][cb];
        ull aA0 = 0, aB0 = 0, aA1 = 0, aB1 = 0, aA2 = 0, aB2 = 0, aA3 = 0, aB3 = 0;
        #pragma unroll
        for (int k = 0; k < 8; k++) {
            const ulonglong2 hv = hp[k];
            aA0 = ffma2(w[0][2 * k], hv.x, aA0); aB0 = ffma2(w[0][2 * k + 1], hv.y, aB0);
            aA1 = ffma2(w[1][2 * k], hv.x, aA1); aB1 = ffma2(w[1][2 * k + 1], hv.y, aB1);
            aA2 = ffma2(w[2][2 * k], hv.x, aA2); aB2 = ffma2(w[2][2 * k + 1], hv.y, aB2);
            aA3 = ffma2(w[3][2 * k], hv.x, aA3); aB3 = ffma2(w[3][2 * k + 1], hv.y, aB3);
        }
        {
            float lo, hi;
            ull s0 = fadd2(aA0, aB0); unpack2(s0, lo, hi); gi += lo + hi;
            ull s1 = fadd2(aA1, aB1); unpack2(s1, lo, hi); gf += lo + hi;
            ull s2 = fadd2(aA2, aB2); unpack2(s2, lo, hi); gg += lo + hi;
            ull s3 = fadd2(aA3, aB3); unpack2(s3, lo, hi); go += lo + hi;
        }

        const float fi = sigf(gi);
        const float ff = sigf(gf);
        const float tg = tanh_fast(gg);
        const float fo = sigf(go);
        c = fmaf(ff, c, fi * tg);
        const float h = fo * tanh_fast(c);
        h_sh[warp][cb ^ 1][lane] = h;
        __syncwarp();

        const int t = dir ? (TT - 1 - s) : s;
        if (L0K) g_h1[((size_t)t * BB + b) * 64 + dir * 32 + lane] = h;
        else     outp[((size_t)b * TT + t) * 64 + dir * 32 + lane] = h;
    };

    for (int s = 0; s < TT; s += 4) {
        step(s + 0, 0, 0);
        step(s + 1, 1, 1);
        step(s + 2, 2, 0);
        step(s + 3, 3, 1);
    }
}

extern "C" void kernel_launch(void* const* d_in, const int* in_sizes, int n_in,
                              void* d_out, int out_size) {
    (void)in_sizes; (void)n_in; (void)out_size;
    const float* oseq = (const float*)d_in[0];
    const float* iseq = (const float*)d_in[1];
    const float* Wih0 = (const float*)d_in[2];
    const float* Whh0 = (const float*)d_in[3];
    const float* bih0 = (const float*)d_in[4];
    const float* bhh0 = (const float*)d_in[5];
    const float* Wih1 = (const float*)d_in[6];
    const float* Whh1 = (const float*)d_in[7];
    const float* bih1 = (const float*)d_in[8];
    const float* bhh1 = (const float*)d_in[9];
    float* out = (float*)d_out;

    precompute<32, true ><<<dim3(148, 2), 256>>>(oseq, iseq, Wih0, bih0, bhh0);
    recurrent<true ><<<dim3(64, 2), 128>>>(Whh0, nullptr);
    precompute<64, false><<<dim3(148, 2), 256>>>(nullptr, nullptr, Wih1, bih1, bhh1);
    recurrent<false><<<dim3(64, 2), 128>>>(Whh1, out);
}